// round 13
// baseline (speedup 1.0000x reference)
#include <cuda_runtime.h>
#include <cuda_fp16.h>

#define HW (2048*2048)
#define SRADII_MAX 589824   // 768^2
#define SCLEAN_MAX 586756   // 766^2
#define RGATE2     585225   // 765^2 : only px with d2>=this can be scatter targets
#define HVWV (2045*2045)

// 32-bit packed winner: (order+1)<<5 | (dh+2)<<3 | (dw+2)<<1 | neg
// src = p + (neg ? -1 : +1) * (dh*2048 + dw).
__device__ unsigned int g_packed[HW];

// Gaussian sigma=2, truncate=4 -> radius 8 ; weight for tap offset o is c_w[|o|]
__constant__ float c_w[9] = {
    0.19947464f, 0.17603575f, 0.12098747f, 0.06475993f,
    0.02699595f, 0.00876430f, 0.00221596f, 0.00043635f, 0.00006692f
};

__device__ __forceinline__ float wtap(int k) {   // k in [0,16], offset k-8
    return c_w[k < 8 ? 8 - k : k - 8];
}

// ---------------------------------------------------------------- smem-tiled scatter
// Block = 64x32 source tile. Candidates accumulate in a 67x35 smem tile (halo -2..+1).
// Owned cells (writer window inside tile) -> plain store; boundary -> global atomicMax.
__global__ __launch_bounds__(256) void k_scatter(const int2* __restrict__ off) {
    int X0 = 2 + (blockIdx.x << 6);
    int Y0 = 2 + (blockIdx.y << 5);
    int TWe = min(64, 2047 - X0);
    int THe = min(32, 2047 - Y0);
    int tid = threadIdx.x;

    // Early out: whole source tile inside ring -> no writers
    {
        int dxa = 1024 - X0, dxb = 1024 - (X0 + TWe - 1);
        int dya = 1024 - Y0, dyb = 1024 - (Y0 + THe - 1);
        if (max(dxa*dxa, dxb*dxb) + max(dya*dya, dyb*dyb) < SRADII_MAX) return;
    }

    __shared__ unsigned int s_t[35][67];      // 2345 cells

    #pragma unroll
    for (int j = 0; j < 10; j++) {
        int i = tid + (j << 8);
        if (i < 35*67) ((unsigned int*)s_t)[i] = 0u;
    }
    __syncthreads();

    #pragma unroll
    for (int j = 0; j < 8; j++) {
        int idx = tid + (j << 8);
        int sy = idx >> 6, sx = idx & 63;
        if (sx >= TWe || sy >= THe) continue;
        int ww = X0 + sx, hh = Y0 + sy;
        int dx = 1024 - ww, dy = 1024 - hh;
        if (dx*dx + dy*dy < SRADII_MAX) continue;

        int local = (hh - 2) * 2045 + (ww - 2);
        int2 o0 = off[local];
        int2 o1 = off[HVWV + local];

        // i=0: own-lin write dominated by i=1's own-lin write; only lin2 needed.
        {
            unsigned o1p1 = (unsigned)(2*local + 1);
            unsigned base = (o1p1 << 5) | ((unsigned)(o0.x + 2) << 3) | ((unsigned)(o0.y + 2) << 1);
            atomicMax(&s_t[sy + 2 + o0.x][sx + 2 + o0.y], base + 32u + 1u);
        }
        // i=1: both writes.
        {
            unsigned o1p1 = (unsigned)(2*HVWV + 2*local + 1);
            unsigned base = (o1p1 << 5) | ((unsigned)(o1.x + 2) << 3) | ((unsigned)(o1.y + 2) << 1);
            atomicMax(&s_t[sy + 2][sx + 2], base);
            atomicMax(&s_t[sy + 2 + o1.x][sx + 2 + o1.y], base + 32u + 1u);
        }
    }
    __syncthreads();

    // Flush 67x35 cells
    #pragma unroll
    for (int j = 0; j < 10; j++) {
        int i = tid + (j << 8);
        if (i >= 35*67) break;
        int cy = i / 67, cx = i - cy * 67;
        int ty = Y0 - 2 + cy, tx = X0 - 2 + cx;
        if (tx < 0 || tx > 2047 || ty < 0 || ty > 2047) continue;
        unsigned val = s_t[cy][cx];
        bool own_x = (max(tx - 1, 2) >= X0) && (min(tx + 2, 2046) <= X0 + TWe - 1);
        bool own_y = (max(ty - 1, 2) >= Y0) && (min(ty + 2, 2046) <= Y0 + THe - 1);
        int g = ty * 2048 + tx;
        if (own_x && own_y) {
            g_packed[g] = val;               // exclusive: plain store (also clears to 0)
        } else if (val) {
            atomicMax(&g_packed[g], val);    // idempotent across replays
        }
    }
}

// ---------------------------------------------------------------- fused gather + H blur + V blur + finalize
// grid (32, 64), block 256. Output tile 64x32, halo 80x48.
// fp16 smem intermediates, fp32 arithmetic.
__global__ __launch_bounds__(256, 4) void k_fused(const float* __restrict__ img,
                                                  float* __restrict__ out) {
    int x0 = blockIdx.x << 6;
    int y0 = blockIdx.y << 5;
    int tid = threadIdx.x;

    int dxa = 1024 - x0, dxb = 1024 - (x0 + 63);
    int maxdx2 = max(dxa*dxa, dxb*dxb);
    int mindx2 = (x0 <= 1024 && 1024 <= x0 + 63) ? 0 : min(dxa*dxa, dxb*dxb);
    int dya = 1024 - y0, dyb = 1024 - (y0 + 31);
    int maxdy2 = max(dya*dya, dyb*dyb);
    int mindy2 = (y0 <= 1024 && 1024 <= y0 + 31) ? 0 : min(dya*dya, dyb*dyb);

    if (maxdx2 + maxdy2 < SCLEAN_MAX) {       // whole tile clean: pure float4 copy
        int fb = ((y0 * 2048 + x0) * 3) >> 2;
        const float4* s = (const float4*)img;
        float4*       d = (float4*)out;
        #pragma unroll
        for (int i = 0; i < 6; i++) {
            int j  = tid + (i << 8);          // 0..1535
            int row = j / 48, col = j - row * 48;
            int fi = fb + row * 1536 + col;
            d[fi] = s[fi];
        }
        return;
    }

    __shared__ __half s_in[3][48][88];        // gathered /255 (80 valid cols)
    __shared__ __half s_h[3][48][66];         // H-blur result (64 valid)

    // ---- load + inline gather (3840 halo pixels, 15 per thread) ----
    const float inv = 1.0f / 255.0f;
    #pragma unroll
    for (int it = 0; it < 15; it++) {
        int i  = tid + (it << 8);
        int hy = i / 80, hx = i - hy * 80;
        int gy = y0 - 8 + hy; gy = gy < 0 ? 0 : (gy > 2047 ? 2047 : gy);
        int gx = x0 - 8 + hx; gx = gx < 0 ? 0 : (gx > 2047 ? 2047 : gx);
        int p  = gy * 2048 + gx;
        int src = p;
        int ddx = 1024 - gx, ddy = 1024 - gy;
        if (ddx*ddx + ddy*ddy >= RGATE2) {
            unsigned v = g_packed[p];
            if (v) {
                int D = (((int)((v >> 3) & 3u)) - 2) * 2048 + (((int)((v >> 1) & 3u)) - 2);
                src = (v & 1u) ? p - D : p + D;
            }
        }
        s_in[0][hy][hx] = __float2half_rn(img[src*3 + 0] * inv);
        s_in[1][hy][hx] = __float2half_rn(img[src*3 + 1] * inv);
        s_in[2][hy][hx] = __float2half_rn(img[src*3 + 2] * inv);
    }
    __syncthreads();

    // ---- H blur: 384 row-units (48 rows x 8 col-blocks), strided over 256 threads ----
    for (int u = tid; u < 384; u += 256) {
        int yy = u >> 3;
        int xb = (u & 7) << 3;
        #pragma unroll
        for (int c = 0; c < 3; c++) {
            float v[24];
            const uint4* up = reinterpret_cast<const uint4*>(&s_in[c][yy][xb]);
            #pragma unroll
            for (int q = 0; q < 3; q++) {
                uint4 u4 = up[q];
                unsigned uw[4] = {u4.x, u4.y, u4.z, u4.w};
                #pragma unroll
                for (int m = 0; m < 4; m++) {
                    float2 f = __half22float2(*reinterpret_cast<__half2*>(&uw[m]));
                    v[8*q + 2*m]     = f.x;
                    v[8*q + 2*m + 1] = f.y;
                }
            }
            float ho[8];
            #pragma unroll
            for (int j = 0; j < 8; j++) {
                float a = 0.0f;
                #pragma unroll
                for (int k = 0; k < 17; k++) a += wtap(k) * v[j + k];
                ho[j] = a;
            }
            #pragma unroll
            for (int q = 0; q < 4; q++)
                *reinterpret_cast<__half2*>(&s_h[c][yy][xb + 2*q]) =
                    __floats2half2_rn(ho[2*q], ho[2*q + 1]);
        }
    }
    __syncthreads();

    // ---- V blur: thread = (column, channel); two 16-row halves ----
    if (tid < 192) {
        int col = tid & 63;
        int ch  = tid >> 6;
        int px  = x0 + col;
        int dxp2 = (1024 - px) * (1024 - px);
        bool mixed = (mindx2 + mindy2) < SCLEAN_MAX;

        #pragma unroll
        for (int half = 0; half < 2; half++) {
            int rbase = half << 4;
            float acc[16];
            #pragma unroll
            for (int r = 0; r < 16; r++) acc[r] = 0.0f;

            #pragma unroll
            for (int k = 0; k < 32; k++) {
                float val = __half2float(s_h[ch][rbase + k][col]);
                #pragma unroll
                for (int r = 0; r < 16; r++) {
                    int t = k - r;
                    if (t >= 0 && t <= 16) acc[r] += wtap(t) * val;
                }
            }

            #pragma unroll
            for (int r = 0; r < 16; r++) {
                int y  = y0 + rbase + r;
                int oi = (y * 2048 + px) * 3 + ch;
                float bv = fminf(fmaxf(acc[r], 0.0f), 1.0f) * 255.0f;
                if (mixed) {
                    int dyp = 1024 - y;
                    if (dxp2 + dyp * dyp < SCLEAN_MAX) bv = img[oi];
                }
                out[oi] = bv;
            }
        }
    }
}

extern "C" void kernel_launch(void* const* d_in, const int* in_sizes, int n_in,
                              void* d_out, int out_size) {
    const float* img;
    const int*   off;
    if (in_sizes[0] == 2048*2048*3) {
        img = (const float*)d_in[0];
        off = (const int*)d_in[1];
    } else {
        img = (const float*)d_in[1];
        off = (const int*)d_in[0];
    }
    float* out = (float*)d_out;

    k_scatter<<<dim3(32, 64), 256>>>((const int2*)off);

    k_fused<<<dim3(32, 64), 256>>>(img, out);
}